// round 15
// baseline (speedup 1.0000x reference)
#include <cuda_runtime.h>
#include <cuda_bf16.h>
#include <math.h>

// Problem constants
#define BB 2
#define SS 2048
#define DD 1024
#define HH 16
#define DK 64
#define NROWS (BB * SS)   // 4096
#define NEL (NROWS * DD)  // 4M
#define WEL (DD * DD)     // 1M

// ---------------------------------------------------------------------------
// Scratch (device globals -- no allocation allowed)
// ---------------------------------------------------------------------------
__device__ __nv_bfloat16 g_qh[NEL], g_ql[NEL];
__device__ __nv_bfloat16 g_kh[NEL], g_kl[NEL];
__device__ __nv_bfloat16 g_vh[NEL], g_vl[NEL];
__device__ __nv_bfloat16 g_oqh[NEL], g_oql[NEL];
__device__ __nv_bfloat16 g_okh[NEL], g_okl[NEL];
__device__ __nv_bfloat16 g_xh[NEL], g_xl[NEL];
__device__ __nv_bfloat16 g_yh[NEL], g_yl[NEL];
__device__ __nv_bfloat16 g_wqh[WEL], g_wql[WEL];
__device__ __nv_bfloat16 g_wkh[WEL], g_wkl[WEL];
__device__ __nv_bfloat16 g_wvh[WEL], g_wvl[WEL];
__device__ __nv_bfloat16 g_woh[WEL], g_wol[WEL];
__device__ float g_ct[SS * DK];
__device__ float g_st[SS * DK];

// ---------------------------------------------------------------------------
// Primitives
// ---------------------------------------------------------------------------
#define LDSM4(R, addr)                                                   \
  asm volatile(                                                          \
      "ldmatrix.sync.aligned.m8n8.x4.shared.b16 {%0,%1,%2,%3},[%4];"     \
      : "=r"((R)[0]), "=r"((R)[1]), "=r"((R)[2]), "=r"((R)[3])           \
      : "r"(addr))

#define LDSM4T(R, addr)                                                  \
  asm volatile(                                                          \
      "ldmatrix.sync.aligned.m8n8.x4.trans.shared.b16 {%0,%1,%2,%3},[%4];" \
      : "=r"((R)[0]), "=r"((R)[1]), "=r"((R)[2]), "=r"((R)[3])           \
      : "r"(addr))

#define MMA16816(C, A, B0, B1)                                           \
  asm volatile(                                                          \
      "mma.sync.aligned.m16n8k16.row.col.f32.bf16.bf16.f32 "             \
      "{%0,%1,%2,%3},{%4,%5,%6,%7},{%8,%9},{%0,%1,%2,%3};"               \
      : "+f"((C)[0]), "+f"((C)[1]), "+f"((C)[2]), "+f"((C)[3])           \
      : "r"((A)[0]), "r"((A)[1]), "r"((A)[2]), "r"((A)[3]), "r"(B0),     \
        "r"(B1))

#define CPA16(dst, src)                                                  \
  asm volatile("cp.async.cg.shared.global [%0], [%1], 16;" ::"r"(dst),   \
               "l"(src))
#define CPA_COMMIT() asm volatile("cp.async.commit_group;" ::)
#define CPA_WAIT(n) asm volatile("cp.async.wait_group %0;" ::"n"(n))

__device__ __forceinline__ unsigned pack_bf16(float a, float b) {
  __nv_bfloat162 t = __halves2bfloat162(__float2bfloat16(a), __float2bfloat16(b));
  return *(unsigned*)&t;
}

// ---------------------------------------------------------------------------
// rope table: ct/st[s][j] = cos/sin(s * 10000^{-(j mod 32)/32})
// ---------------------------------------------------------------------------
__global__ void rope_table_kernel(float* __restrict__ ct,
                                  float* __restrict__ st) {
  int idx = blockIdx.x * blockDim.x + threadIdx.x;  // SS*DK = 131072
  int s = idx >> 6;
  int m = idx & 31;
  const float L = 0.41524101186091903f;  // log2(10000)/32
  float a = (float)s * exp2f(-(float)m * L);
  const double INV2PI = 0.15915494309189535;
  const double TWOPI = 6.283185307179586;
  double r = (double)a - floor((double)a * INV2PI) * TWOPI;
  ct[idx] = cosf((float)r);
  st[idx] = sinf((float)r);
}

// ---------------------------------------------------------------------------
// batched splits: fp32 -> (hi, lo) bf16 planes. gridDim.z selects tensor.
// ---------------------------------------------------------------------------
__global__ void split3_kernel(const float* __restrict__ x0,
                              const float* __restrict__ x1,
                              const float* __restrict__ x2,
                              __nv_bfloat16* h0, __nv_bfloat16* l0,
                              __nv_bfloat16* h1, __nv_bfloat16* l1,
                              __nv_bfloat16* h2, __nv_bfloat16* l2) {
  const float* x;
  __nv_bfloat16 *hi, *lo;
  if (blockIdx.z == 0) { x = x0; hi = h0; lo = l0; }
  else if (blockIdx.z == 1) { x = x1; hi = h1; lo = l1; }
  else { x = x2; hi = h2; lo = l2; }
  int i = (blockIdx.x * blockDim.x + threadIdx.x) << 2;
  float4 v = *(const float4*)(x + i);
  float f[4] = {v.x, v.y, v.z, v.w};
  __nv_bfloat16 h[4], l[4];
#pragma unroll
  for (int j = 0; j < 4; j++) {
    h[j] = __float2bfloat16(f[j]);
    l[j] = __float2bfloat16(f[j] - __bfloat162float(h[j]));
  }
  *(__nv_bfloat162*)(hi + i) = __halves2bfloat162(h[0], h[1]);
  *(__nv_bfloat162*)(hi + i + 2) = __halves2bfloat162(h[2], h[3]);
  *(__nv_bfloat162*)(lo + i) = __halves2bfloat162(l[0], l[1]);
  *(__nv_bfloat162*)(lo + i + 2) = __halves2bfloat162(l[2], l[3]);
}

__global__ void split4_kernel(const float* __restrict__ x0,
                              const float* __restrict__ x1,
                              const float* __restrict__ x2,
                              const float* __restrict__ x3,
                              __nv_bfloat16* h0, __nv_bfloat16* l0,
                              __nv_bfloat16* h1, __nv_bfloat16* l1,
                              __nv_bfloat16* h2, __nv_bfloat16* l2,
                              __nv_bfloat16* h3, __nv_bfloat16* l3) {
  const float* x;
  __nv_bfloat16 *hi, *lo;
  if (blockIdx.z == 0) { x = x0; hi = h0; lo = l0; }
  else if (blockIdx.z == 1) { x = x1; hi = h1; lo = l1; }
  else if (blockIdx.z == 2) { x = x2; hi = h2; lo = l2; }
  else { x = x3; hi = h3; lo = l3; }
  int i = (blockIdx.x * blockDim.x + threadIdx.x) << 2;
  float4 v = *(const float4*)(x + i);
  float f[4] = {v.x, v.y, v.z, v.w};
  __nv_bfloat16 h[4], l[4];
#pragma unroll
  for (int j = 0; j < 4; j++) {
    h[j] = __float2bfloat16(f[j]);
    l[j] = __float2bfloat16(f[j] - __bfloat162float(h[j]));
  }
  *(__nv_bfloat162*)(hi + i) = __halves2bfloat162(h[0], h[1]);
  *(__nv_bfloat162*)(hi + i + 2) = __halves2bfloat162(h[2], h[3]);
  *(__nv_bfloat162*)(lo + i) = __halves2bfloat162(l[0], l[1]);
  *(__nv_bfloat162*)(lo + i + 2) = __halves2bfloat162(l[2], l[3]);
}

// ---------------------------------------------------------------------------
// GEMM core (cp.async 2-stage, bf16x3). CTA 128x128, K_STEP 32.
// 128 threads = 4 warps (2m x 2n), warp tile 64x64: per ks-block 16 LDSM.x4
// feed 96 HMMA (0.167 vs 0.25 before) -- cuts smem LDSM bandwidth per FLOP
// by 33% (R14 showed the tensor pipe pinned ~48% with the smaller warp tile
// regardless of occupancy/order => smem-BW co-limited).
// ---------------------------------------------------------------------------
#define SA 40
#define PLANE (128 * SA)            // 5120 bf16 per plane
#define BUFE (4 * PLANE)            // AHI, ALO, BHI, BLO
#define GEMM_SMEM (2 * BUFE * 2)    // 81920 bytes

struct GemmCore {
  unsigned sb32;
  const __nv_bfloat16 *xh, *xl, *wh, *wl;
  unsigned sdst;
  int a_r, a_c, b_r, b_c;

  __device__ __forceinline__ void init(const __nv_bfloat16* Xh,
                                       const __nv_bfloat16* Xl,
                                       const __nv_bfloat16* Wh,
                                       const __nv_bfloat16* Wl, int m0, int n0,
                                       unsigned smem_base, int t) {
    sb32 = smem_base;
    const int lane = t & 31;
    const int w = t >> 5;        // 0..3
    const int mw = w & 1;        // m offset mw*64
    const int nw = w >> 1;       // n offset nw*64
    const int grow = t;          // each thread owns one row (0..127)
    xh = Xh + (size_t)(m0 + grow) * 1024;
    xl = Xl + (size_t)(m0 + grow) * 1024;
    wh = Wh + (size_t)(n0 + grow) * 1024;
    wl = Wl + (size_t)(n0 + grow) * 1024;
    sdst = sb32 + (unsigned)((grow * SA) << 1);
    a_r = mw * 64 + (lane & 15);
    a_c = (lane & 16) ? 8 : 0;
    b_r = nw * 64 + (lane & 7) + ((lane & 16) ? 8 : 0);
    b_c = (lane & 8) ? 8 : 0;
  }

  __device__ __forceinline__ void issue(int kt, int bufi) {
    const unsigned d = sdst + (unsigned)(bufi * (BUFE * 2));
    const int o_ = kt * 32;
#pragma unroll
    for (int q = 0; q < 4; q++) {
      CPA16(d + q * 16, xh + o_ + q * 8);
      CPA16(d + PLANE * 2 + q * 16, xl + o_ + q * 8);
      CPA16(d + 2 * PLANE * 2 + q * 16, wh + o_ + q * 8);
      CPA16(d + 3 * PLANE * 2 + q * 16, wl + o_ + q * 8);
    }
    CPA_COMMIT();
  }

  __device__ __forceinline__ void run(float acc[4][8][4]) {
    issue(0, 0);
    CPA_WAIT(0);
    __syncthreads();
    int buf = 0;
    for (int kt = 0; kt < 32; kt++) {
      if (kt < 31) issue(kt + 1, buf ^ 1);
      const unsigned bbase = sb32 + buf * (BUFE * 2);
#pragma unroll
      for (int ks = 0; ks < 2; ks++) {
        const int k0 = ks << 4;
        unsigned ahi[4][4], alo[4][4], bhi[4][4], blo[4][4];
        unsigned aaddr = bbase + (unsigned)((a_r * SA + k0 + a_c) << 1);
#pragma unroll
        for (int mf = 0; mf < 4; mf++) {
          LDSM4(ahi[mf], aaddr + mf * (16 * SA * 2));
          LDSM4(alo[mf], aaddr + mf * (16 * SA * 2) + PLANE * 2);
        }
        unsigned baddr =
            bbase + (unsigned)(((2 * PLANE) + b_r * SA + k0 + b_c) << 1);
#pragma unroll
        for (int g2 = 0; g2 < 4; g2++) {
          LDSM4(bhi[g2], baddr + g2 * (16 * SA * 2));
          LDSM4(blo[g2], baddr + g2 * (16 * SA * 2) + PLANE * 2);
        }
#pragma unroll
        for (int c = 0; c < 3; c++)
#pragma unroll
          for (int mf = 0; mf < 4; mf++)
#pragma unroll
            for (int nf = 0; nf < 8; nf++) {
              const int g = nf >> 1, hh = (nf & 1) << 1;
              if (c == 0)
                MMA16816(acc[mf][nf], ahi[mf], bhi[g][hh], bhi[g][hh + 1]);
              else if (c == 1)
                MMA16816(acc[mf][nf], ahi[mf], blo[g][hh], blo[g][hh + 1]);
              else
                MMA16816(acc[mf][nf], alo[mf], bhi[g][hh], bhi[g][hh + 1]);
            }
      }
      if (kt < 31) {
        CPA_WAIT(0);
        __syncthreads();
        buf ^= 1;
      }
    }
  }
};

// ---------------------------------------------------------------------------
// Merged q/k/v projection GEMM. grid (8, 32, 3); z: 0=q(rope),1=k(rope),2=v.
// 128 threads, 2 CTAs/SM.
// ---------------------------------------------------------------------------
__global__ __launch_bounds__(128, 2) void gemm_qkv(
    const __nv_bfloat16* __restrict__ Qh, const __nv_bfloat16* __restrict__ Ql,
    const __nv_bfloat16* __restrict__ Kh, const __nv_bfloat16* __restrict__ Kl,
    const __nv_bfloat16* __restrict__ Vh, const __nv_bfloat16* __restrict__ Vl,
    const __nv_bfloat16* __restrict__ Wqh, const __nv_bfloat16* __restrict__ Wql,
    const __nv_bfloat16* __restrict__ Wkh, const __nv_bfloat16* __restrict__ Wkl,
    const __nv_bfloat16* __restrict__ Wvh, const __nv_bfloat16* __restrict__ Wvl,
    __nv_bfloat16* __restrict__ Oqh, __nv_bfloat16* __restrict__ Oql,
    __nv_bfloat16* __restrict__ Okh, __nv_bfloat16* __restrict__ Okl,
    __nv_bfloat16* __restrict__ Ovh, __nv_bfloat16* __restrict__ Ovl,
    const float* __restrict__ CT, const float* __restrict__ ST) {
  extern __shared__ __nv_bfloat16 sb[];
  const int z = blockIdx.z;
  const __nv_bfloat16 *Xh, *Xl, *Wh, *Wl;
  __nv_bfloat16 *Yh, *Yl;
  if (z == 0) { Xh = Qh; Xl = Ql; Wh = Wqh; Wl = Wql; Yh = Oqh; Yl = Oql; }
  else if (z == 1) { Xh = Kh; Xl = Kl; Wh = Wkh; Wl = Wkl; Yh = Okh; Yl = Okl; }
  else { Xh = Vh; Xl = Vl; Wh = Wvh; Wl = Wvl; Yh = Ovh; Yl = Ovl; }

  const int t = threadIdx.x;
  const int lane = t & 31;
  const int w = t >> 5;
  const int m0 = blockIdx.y * 128;
  const int n0 = blockIdx.x * 128;

  GemmCore core;
  core.init(Xh, Xl, Wh, Wl, m0, n0,
            (unsigned)__cvta_generic_to_shared(sb), t);
  float acc[4][8][4] = {};
  core.run(acc);

  const int erow = m0 + (w & 1) * 64 + (lane >> 2);
  const int ecol = n0 + (w >> 1) * 64 + ((lane & 3) << 1);
  const bool dorope = (z < 2);
#pragma unroll
  for (int mf = 0; mf < 4; mf++)
#pragma unroll
    for (int nf = 0; nf < 8; nf++) {
      const int colbase = ecol + nf * 8;
      const int j = colbase & 63;
#pragma unroll
      for (int p = 0; p < 2; p++) {
        const int row = erow + mf * 16 + p * 8;
        float a0 = acc[mf][nf][2 * p], a1 = acc[mf][nf][2 * p + 1];
        if (dorope) {
          const int s = row & (SS - 1);
          float c0 = CT[s * 64 + j], s0v = ST[s * 64 + j];
          float c1 = CT[s * 64 + j + 1], s1v = ST[s * 64 + j + 1];
          float r0 = a0 * c0 - a1 * s0v;
          float r1 = a0 * s1v + a1 * c1;
          a0 = r0;
          a1 = r1;
        }
        __nv_bfloat16 ha = __float2bfloat16(a0), hb = __float2bfloat16(a1);
        size_t addr = (size_t)row * 1024 + colbase;
        *(unsigned*)&Yh[addr] = pack_bf16(a0, a1);
        *(unsigned*)&Yl[addr] = pack_bf16(a0 - __bfloat162float(ha),
                                          a1 - __bfloat162float(hb));
      }
    }
}

// ---------------------------------------------------------------------------
// Final projection GEMM: planes -> fp32 out.
// ---------------------------------------------------------------------------
__global__ __launch_bounds__(128, 2) void gemm_out(
    const __nv_bfloat16* __restrict__ Xh, const __nv_bfloat16* __restrict__ Xl,
    const __nv_bfloat16* __restrict__ Wh, const __nv_bfloat16* __restrict__ Wl,
    float* __restrict__ Y) {
  extern __shared__ __nv_bfloat16 sb[];
  const int t = threadIdx.x;
  const int lane = t & 31;
  const int w = t >> 5;
  const int m0 = blockIdx.y * 128;
  const int n0 = blockIdx.x * 128;

  GemmCore core;
  core.init(Xh, Xl, Wh, Wl, m0, n0,
            (unsigned)__cvta_generic_to_shared(sb), t);
  float acc[4][8][4] = {};
  core.run(acc);

  const int erow = m0 + (w & 1) * 64 + (lane >> 2);
  const int ecol = n0 + (w >> 1) * 64 + ((lane & 3) << 1);
#pragma unroll
  for (int mf = 0; mf < 4; mf++)
#pragma unroll
    for (int nf = 0; nf < 8; nf++) {
      float* yp = Y + (size_t)(erow + mf * 16) * 1024 + ecol + nf * 8;
      float2 lo2 = {acc[mf][nf][0], acc[mf][nf][1]};
      float2 hi2 = {acc[mf][nf][2], acc[mf][nf][3]};
      *(float2*)yp = lo2;
      *(float2*)(yp + 8 * 1024) = hi2;
    }
}

// ---------------------------------------------------------------------------
// MMA flash attention: causal, bf16x3, cp.async double buffered K/V.
// (unchanged from R14 -- known-good)
// ---------------------------------------------------------------------------
#define AST 72
#define PL2 (64 * AST * 2)
#define STAGE_B (4 * PL2)
#define ATTN_SMEM (2 * STAGE_B)  // 73728 B

__global__ __launch_bounds__(128, 2) void attn_mma(
    const __nv_bfloat16* __restrict__ Qh, const __nv_bfloat16* __restrict__ Ql,
    const __nv_bfloat16* __restrict__ Kh, const __nv_bfloat16* __restrict__ Kl,
    const __nv_bfloat16* __restrict__ Vh, const __nv_bfloat16* __restrict__ Vl,
    __nv_bfloat16* __restrict__ XoH, __nv_bfloat16* __restrict__ XoL) {
  extern __shared__ __nv_bfloat16 as_[];
  const unsigned s_base = (unsigned)__cvta_generic_to_shared(as_);

  const int t = threadIdx.x;
  const int lane = t & 31;
  const int wi = t >> 5;
  const int b = blockIdx.x >> 4;
  const int h = blockIdx.x & 15;
  const int qt = (int)gridDim.y - 1 - (int)blockIdx.y;
  const size_t base = (size_t)b * SS * DD + h * DK;

  {
    __nv_bfloat16* q0h = as_;
    __nv_bfloat16* q0l = as_ + 64 * AST;
    for (int idx = t; idx < 512; idx += 128) {
      int r = idx >> 3, c = (idx & 7) << 3;
      size_t g = base + (size_t)(qt * 64 + r) * DD + c;
      *(uint4*)&q0h[r * AST + c] = *(const uint4*)&Qh[g];
      *(uint4*)&q0l[r * AST + c] = *(const uint4*)&Ql[g];
    }
  }
  __syncthreads();
  const int a_r = wi * 16 + (lane & 15);
  const int a_c = (lane & 16) ? 8 : 0;
  unsigned qfh[4][4], qfl[4][4];
#pragma unroll
  for (int kc = 0; kc < 4; kc++) {
    unsigned ad = s_base + (unsigned)((a_r * AST + kc * 16 + a_c) << 1);
    LDSM4(qfh[kc], ad);
    LDSM4(qfl[kc], ad + PL2);
  }
  __syncthreads();

  auto issue_tile = [&](int j, int bufi) {
    const unsigned kb = s_base + bufi * STAGE_B;
    for (int idx = t; idx < 512; idx += 128) {
      int r = idx >> 3, c = (idx & 7) << 3;
      size_t g = base + (size_t)(j * 64 + r) * DD + c;
      unsigned off = (unsigned)((r * AST + c) << 1);
      CPA16(kb + off, Kh + g);
      CPA16(kb + PL2 + off, Kl + g);
      CPA16(kb + 2 * PL2 + off, Vh + g);
      CPA16(kb + 3 * PL2 + off, Vl + g);
    }
    CPA_COMMIT();
  };

  const int b_r = (lane & 7) + ((lane & 16) ? 8 : 0);
  const int b_c = (lane & 8) ? 8 : 0;
  const int v_r = lane & 15;
  const int v_c = ((lane >> 4) & 1) << 3;

  float o[8][4] = {};
  float mrow[2] = {-INFINITY, -INFINITY};
  float lrow[2] = {0.f, 0.f};
  const int grow0 = qt * 64 + wi * 16 + (lane >> 2);
  const int gcol0 = (lane & 3) << 1;

  issue_tile(0, 0);
  int buf = 0;
  for (int j = 0; j <= qt; j++) {
    if (j < qt) {
      issue_tile(j + 1, buf ^ 1);
      CPA_WAIT(1);
    } else {
      CPA_WAIT(0);
    }
    __syncthreads();
    const unsigned kb = s_base + buf * STAGE_B;
    const unsigned vb = kb + 2 * PL2;

    float sc[8][4] = {};
#pragma unroll
    for (int kc = 0; kc < 4; kc++) {
      unsigned bh[4][4], bl[4][4];
#pragma unroll
      for (int g2 = 0; g2 < 4; g2++) {
        unsigned ad =
            kb + (unsigned)(((g2 * 16 + b_r) * AST + kc * 16 + b_c) << 1);
        LDSM4(bh[g2], ad);
        LDSM4(bl[g2], ad + PL2);
      }
#pragma unroll
      for (int c = 0; c < 3; c++)
#pragma unroll
        for (int nf = 0; nf < 8; nf++) {
          const int g2 = nf >> 1, hh = (nf & 1) << 1;
          if (c == 0)
            MMA16816(sc[nf], qfh[kc], bh[g2][hh], bh[g2][hh + 1]);
          else if (c == 1)
            MMA16816(sc[nf], qfh[kc], bl[g2][hh], bl[g2][hh + 1]);
          else
            MMA16816(sc[nf], qfl[kc], bh[g2][hh], bh[g2][hh + 1]);
        }
    }

    const float SC = 0.125f;
    if (j == qt) {
#pragma unroll
      for (int nf = 0; nf < 8; nf++)
#pragma unroll
        for (int e = 0; e < 4; e++) {
          int col = j * 64 + nf * 8 + gcol0 + (e & 1);
          int row = grow0 + ((e >> 1) << 3);
          sc[nf][e] = (col > row) ? -INFINITY : sc[nf][e] * SC;
        }
    } else {
#pragma unroll
      for (int nf = 0; nf < 8; nf++)
#pragma unroll
        for (int e = 0; e < 4; e++) sc[nf][e] *= SC;
    }

#pragma unroll
    for (int i = 0; i < 2; i++) {
      float tm = -INFINITY;
#pragma unroll
      for (int nf = 0; nf < 8; nf++)
        tm = fmaxf(tm, fmaxf(sc[nf][2 * i], sc[nf][2 * i + 1]));
      tm = fmaxf(tm, __shfl_xor_sync(0xffffffffu, tm, 1));
      tm = fmaxf(tm, __shfl_xor_sync(0xffffffffu, tm, 2));
      float mn = fmaxf(mrow[i], tm);
      float corr = __expf(mrow[i] - mn);
      float ps = 0.f;
#pragma unroll
      for (int nf = 0; nf < 8; nf++) {
        float p0 = __expf(sc[nf][2 * i] - mn);
        float p1 = __expf(sc[nf][2 * i + 1] - mn);
        sc[nf][2 * i] = p0;
        sc[nf][2 * i + 1] = p1;
        ps += p0 + p1;
      }
      ps += __shfl_xor_sync(0xffffffffu, ps, 1);
      ps += __shfl_xor_sync(0xffffffffu, ps, 2);
      lrow[i] = lrow[i] * corr + ps;
      mrow[i] = mn;
#pragma unroll
      for (int nf = 0; nf < 8; nf++) {
        o[nf][2 * i] *= corr;
        o[nf][2 * i + 1] *= corr;
      }
    }

#pragma unroll
    for (int kc = 0; kc < 4; kc++) {
      unsigned pa[4], pl[4];
#pragma unroll
      for (int rr = 0; rr < 2; rr++) {
        float f0 = sc[2 * kc + rr][0], f1 = sc[2 * kc + rr][1];
        float f2 = sc[2 * kc + rr][2], f3 = sc[2 * kc + rr][3];
        __nv_bfloat16 h0 = __float2bfloat16(f0), h1 = __float2bfloat16(f1);
        __nv_bfloat16 h2 = __float2bfloat16(f2), h3 = __float2bfloat16(f3);
        pa[2 * rr] = pack_bf16(f0, f1);
        pa[2 * rr + 1] = pack_bf16(f2, f3);
        pl[2 * rr] = pack_bf16(f0 - __bfloat162float(h0),
                               f1 - __bfloat162float(h1));
        pl[2 * rr + 1] = pack_bf16(f2 - __bfloat162float(h2),
                                   f3 - __bfloat162float(h3));
      }
      unsigned wvh[4][4], wvl[4][4];
#pragma unroll
      for (int g2 = 0; g2 < 4; g2++) {
        unsigned ad =
            vb + (unsigned)(((kc * 16 + v_r) * AST + g2 * 16 + v_c) << 1);
        LDSM4T(wvh[g2], ad);
        LDSM4T(wvl[g2], ad + PL2);
      }
#pragma unroll
      for (int c = 0; c < 3; c++)
#pragma unroll
        for (int nf = 0; nf < 8; nf++) {
          const int g2 = nf >> 1, hh = (nf & 1) << 1;
          if (c == 0)
            MMA16816(o[nf], pa, wvh[g2][hh], wvh[g2][hh + 1]);
          else if (c == 1)
            MMA16816(o[nf], pa, wvl[g2][hh], wvl[g2][hh + 1]);
          else
            MMA16816(o[nf], pl, wvh[g2][hh], wvh[g2][hh + 1]);
        }
    }
    __syncthreads();
    buf ^= 1;
  }

#pragma unroll
  for (int i = 0; i < 2; i++) {
    float inv = 1.f / lrow[i];
    int row = grow0 + i * 8;
#pragma unroll
    for (int nf = 0; nf < 8; nf++) {
      float a = o[nf][2 * i] * inv, b2 = o[nf][2 * i + 1] * inv;
      __nv_bfloat16 ha = __float2bfloat16(a), hb = __float2bfloat16(b2);
      size_t addr = (size_t)(b * SS + row) * DD + h * DK + nf * 8 + gcol0;
      *(unsigned*)&XoH[addr] = pack_bf16(a, b2);
      *(unsigned*)&XoL[addr] =
          pack_bf16(a - __bfloat162float(ha), b2 - __bfloat162float(hb));
    }
  }
}

// ---------------------------------------------------------------------------
// kernel_launch
// Inputs: 0=q, 1=k, 2=v, 3=mask (ignored: tril causal), 4=wq, 5=wk, 6=wv, 7=wo
// ---------------------------------------------------------------------------
extern "C" void kernel_launch(void* const* d_in, const int* in_sizes, int n_in,
                              void* d_out, int out_size) {
  (void)in_sizes; (void)n_in; (void)out_size;
  const float* q = (const float*)d_in[0];
  const float* k = (const float*)d_in[1];
  const float* v = (const float*)d_in[2];
  const float* wq = (const float*)d_in[4];
  const float* wk = (const float*)d_in[5];
  const float* wv = (const float*)d_in[6];
  const float* wo = (const float*)d_in[7];
  float* out = (float*)d_out;

  __nv_bfloat16 *qh, *ql, *kh, *kl, *vh, *vl;
  __nv_bfloat16 *oqh, *oql, *okh, *okl, *xh, *xl, *yh, *yl;
  cudaGetSymbolAddress((void**)&qh, g_qh); cudaGetSymbolAddress((void**)&ql, g_ql);
  cudaGetSymbolAddress((void**)&kh, g_kh); cudaGetSymbolAddress((void**)&kl, g_kl);
  cudaGetSymbolAddress((void**)&vh, g_vh); cudaGetSymbolAddress((void**)&vl, g_vl);
  cudaGetSymbolAddress((void**)&oqh, g_oqh); cudaGetSymbolAddress((void**)&oql, g_oql);
  cudaGetSymbolAddress((void**)&okh, g_okh); cudaGetSymbolAddress((void**)&okl, g_okl);
  cudaGetSymbolAddress((void**)&xh, g_xh); cudaGetSymbolAddress((void**)&xl, g_xl);
  cudaGetSymbolAddress((void**)&yh, g_yh); cudaGetSymbolAddress((void**)&yl, g_yl);
  __nv_bfloat16 *wqh, *wql, *wkh, *wkl, *wvh, *wvl, *woh, *wol;
  cudaGetSymbolAddress((void**)&wqh, g_wqh); cudaGetSymbolAddress((void**)&wql, g_wql);
  cudaGetSymbolAddress((void**)&wkh, g_wkh); cudaGetSymbolAddress((void**)&wkl, g_wkl);
  cudaGetSymbolAddress((void**)&wvh, g_wvh); cudaGetSymbolAddress((void**)&wvl, g_wvl);
  cudaGetSymbolAddress((void**)&woh, g_woh); cudaGetSymbolAddress((void**)&wol, g_wol);
  float *ct, *st;
  cudaGetSymbolAddress((void**)&ct, g_ct);
  cudaGetSymbolAddress((void**)&st, g_st);

  cudaFuncSetAttribute(gemm_qkv, cudaFuncAttributeMaxDynamicSharedMemorySize,
                       GEMM_SMEM);
  cudaFuncSetAttribute(gemm_out, cudaFuncAttributeMaxDynamicSharedMemorySize,
                       GEMM_SMEM);
  cudaFuncSetAttribute(attn_mma, cudaFuncAttributeMaxDynamicSharedMemorySize,
                       ATTN_SMEM);

  // splits + rope tables
  split3_kernel<<<dim3(NEL / 1024, 1, 3), 256>>>(q, k, v, qh, ql, kh, kl, vh,
                                                 vl);
  split4_kernel<<<dim3(WEL / 1024, 1, 4), 256>>>(
      wq, wk, wv, wo, wqh, wql, wkh, wkl, wvh, wvl, woh, wol);
  rope_table_kernel<<<(SS * DK) / 256, 256>>>(ct, st);

  // fused q/k/v projections (+rope on q/k), bf16 plane outputs
  gemm_qkv<<<dim3(8, 32, 3), 128, GEMM_SMEM>>>(
      qh, ql, kh, kl, vh, vl, wqh, wql, wkh, wkl, wvh, wvl, oqh, oql, okh, okl,
      xh, xl, ct, st);

  // attention
  attn_mma<<<dim3(BB * HH, SS / 64), 128, ATTN_SMEM>>>(oqh, oql, okh, okl, xh,
                                                       xl, yh, yl);

  // output projection
  gemm_out<<<dim3(8, 32), 128, GEMM_SMEM>>>(yh, yl, woh, wol, out);
}

// round 17
// speedup vs baseline: 1.1655x; 1.1655x over previous
#include <cuda_runtime.h>
#include <cuda_bf16.h>
#include <math.h>

// Problem constants
#define BB 2
#define SS 2048
#define DD 1024
#define HH 16
#define DK 64
#define NROWS (BB * SS)   // 4096
#define NEL (NROWS * DD)  // 4M
#define WEL (DD * DD)     // 1M

// ---------------------------------------------------------------------------
// Scratch (device globals -- no allocation allowed)
// ---------------------------------------------------------------------------
__device__ __nv_bfloat16 g_qh[NEL], g_ql[NEL];
__device__ __nv_bfloat16 g_kh[NEL], g_kl[NEL];
__device__ __nv_bfloat16 g_vh[NEL], g_vl[NEL];
__device__ __nv_bfloat16 g_oqh[NEL], g_oql[NEL];
__device__ __nv_bfloat16 g_okh[NEL], g_okl[NEL];
__device__ __nv_bfloat16 g_xh[NEL], g_xl[NEL];
__device__ __nv_bfloat16 g_yh[NEL], g_yl[NEL];
__device__ __nv_bfloat16 g_wqh[WEL], g_wql[WEL];
__device__ __nv_bfloat16 g_wkh[WEL], g_wkl[WEL];
__device__ __nv_bfloat16 g_wvh[WEL], g_wvl[WEL];
__device__ __nv_bfloat16 g_woh[WEL], g_wol[WEL];
__device__ float g_ct[SS * DK];
__device__ float g_st[SS * DK];

// ---------------------------------------------------------------------------
// Primitives
// ---------------------------------------------------------------------------
#define LDSM4(R, addr)                                                   \
  asm volatile(                                                          \
      "ldmatrix.sync.aligned.m8n8.x4.shared.b16 {%0,%1,%2,%3},[%4];"     \
      : "=r"((R)[0]), "=r"((R)[1]), "=r"((R)[2]), "=r"((R)[3])           \
      : "r"(addr))

#define LDSM4T(R, addr)                                                  \
  asm volatile(                                                          \
      "ldmatrix.sync.aligned.m8n8.x4.trans.shared.b16 {%0,%1,%2,%3},[%4];" \
      : "=r"((R)[0]), "=r"((R)[1]), "=r"((R)[2]), "=r"((R)[3])           \
      : "r"(addr))

#define MMA16816(C, A, B0, B1)                                           \
  asm volatile(                                                          \
      "mma.sync.aligned.m16n8k16.row.col.f32.bf16.bf16.f32 "             \
      "{%0,%1,%2,%3},{%4,%5,%6,%7},{%8,%9},{%0,%1,%2,%3};"               \
      : "+f"((C)[0]), "+f"((C)[1]), "+f"((C)[2]), "+f"((C)[3])           \
      : "r"((A)[0]), "r"((A)[1]), "r"((A)[2]), "r"((A)[3]), "r"(B0),     \
        "r"(B1))

#define CPA16(dst, src)                                                  \
  asm volatile("cp.async.cg.shared.global [%0], [%1], 16;" ::"r"(dst),   \
               "l"(src))
#define CPA_COMMIT() asm volatile("cp.async.commit_group;" ::)
#define CPA_WAIT(n) asm volatile("cp.async.wait_group %0;" ::"n"(n))

__device__ __forceinline__ unsigned pack_bf16(float a, float b) {
  __nv_bfloat162 t = __halves2bfloat162(__float2bfloat16(a), __float2bfloat16(b));
  return *(unsigned*)&t;
}

// ---------------------------------------------------------------------------
// prep kernel: one launch does all splits + the rope tables.
// grid (NEL/1024, 1, 8); z 0..2: q/k/v splits (full grid);
// z 3..6: weight splits (first WEL/1024 blocks); z 7: rope tables.
// ---------------------------------------------------------------------------
__device__ __forceinline__ void split_one(const float* __restrict__ x,
                                          __nv_bfloat16* __restrict__ hi,
                                          __nv_bfloat16* __restrict__ lo,
                                          int i) {
  float4 v = *(const float4*)(x + i);
  float f[4] = {v.x, v.y, v.z, v.w};
  __nv_bfloat16 h[4], l[4];
#pragma unroll
  for (int j = 0; j < 4; j++) {
    h[j] = __float2bfloat16(f[j]);
    l[j] = __float2bfloat16(f[j] - __bfloat162float(h[j]));
  }
  *(__nv_bfloat162*)(hi + i) = __halves2bfloat162(h[0], h[1]);
  *(__nv_bfloat162*)(hi + i + 2) = __halves2bfloat162(h[2], h[3]);
  *(__nv_bfloat162*)(lo + i) = __halves2bfloat162(l[0], l[1]);
  *(__nv_bfloat162*)(lo + i + 2) = __halves2bfloat162(l[2], l[3]);
}

__global__ void prep_kernel(
    const float* __restrict__ q, const float* __restrict__ k,
    const float* __restrict__ v, const float* __restrict__ wq,
    const float* __restrict__ wk, const float* __restrict__ wv,
    const float* __restrict__ wo,
    __nv_bfloat16* qh, __nv_bfloat16* ql, __nv_bfloat16* kh, __nv_bfloat16* kl,
    __nv_bfloat16* vh, __nv_bfloat16* vl,
    __nv_bfloat16* wqh, __nv_bfloat16* wql, __nv_bfloat16* wkh,
    __nv_bfloat16* wkl, __nv_bfloat16* wvh, __nv_bfloat16* wvl,
    __nv_bfloat16* woh, __nv_bfloat16* wol,
    float* __restrict__ ct, float* __restrict__ st) {
  const int z = blockIdx.z;
  const int i = (blockIdx.x * blockDim.x + threadIdx.x) << 2;
  if (z == 0) { split_one(q, qh, ql, i); }
  else if (z == 1) { split_one(k, kh, kl, i); }
  else if (z == 2) { split_one(v, vh, vl, i); }
  else if (z <= 6) {
    if (i >= WEL) return;
    if (z == 3) split_one(wq, wqh, wql, i);
    else if (z == 4) split_one(wk, wkh, wkl, i);
    else if (z == 5) split_one(wv, wvh, wvl, i);
    else split_one(wo, woh, wol, i);
  } else {
    // rope tables: ct/st[s][j] = cos/sin(s * 10000^{-(j mod 32)/32})
    int idx = blockIdx.x * blockDim.x + threadIdx.x;  // 1 elem/thread
    if (idx >= SS * DK) return;
    int s = idx >> 6;
    int m = idx & 31;
    const float L = 0.41524101186091903f;  // log2(10000)/32
    float a = (float)s * exp2f(-(float)m * L);
    const double INV2PI = 0.15915494309189535;
    const double TWOPI = 6.283185307179586;
    double r = (double)a - floor((double)a * INV2PI) * TWOPI;
    ct[idx] = cosf((float)r);
    st[idx] = sinf((float)r);
  }
}

// ---------------------------------------------------------------------------
// GEMM core (cp.async 2-stage, bf16x3). CTA 128x128, K_STEP 32,
// 8 warps (2m x 4n), warp 64x32 -- the R14 configuration (best measured:
// 48% tensor, 2 CTAs/SM). Mainloop frozen: 5 variants tested, this wins.
// ---------------------------------------------------------------------------
#define SA 40
#define PLANE (128 * SA)            // 5120 bf16 per plane
#define BUFE (4 * PLANE)            // AHI, ALO, BHI, BLO
#define GEMM_SMEM (2 * BUFE * 2)    // 81920 bytes

struct GemmCore {
  unsigned sb32;
  const __nv_bfloat16 *xh, *xl, *wh, *wl;
  unsigned sdst;
  int a_r, a_c, b_r, b_c;

  __device__ __forceinline__ void init(const __nv_bfloat16* Xh,
                                       const __nv_bfloat16* Xl,
                                       const __nv_bfloat16* Wh,
                                       const __nv_bfloat16* Wl, int m0, int n0,
                                       unsigned smem_base, int t) {
    sb32 = smem_base;
    const int lane = t & 31;
    const int w = t >> 5;
    const int mw = w & 1;
    const int nw = w >> 1;
    const int grow = t >> 1;
    const int gkh = (t & 1) << 4;
    xh = Xh + (size_t)(m0 + grow) * 1024 + gkh;
    xl = Xl + (size_t)(m0 + grow) * 1024 + gkh;
    wh = Wh + (size_t)(n0 + grow) * 1024 + gkh;
    wl = Wl + (size_t)(n0 + grow) * 1024 + gkh;
    sdst = sb32 + (unsigned)((grow * SA + gkh) << 1);
    a_r = mw * 64 + (lane & 15);
    a_c = (lane & 16) ? 8 : 0;
    b_r = nw * 32 + (lane & 7) + ((lane & 16) ? 8 : 0);
    b_c = (lane & 8) ? 8 : 0;
  }

  __device__ __forceinline__ void issue(int kt, int bufi) {
    const unsigned d = sdst + (unsigned)(bufi * (BUFE * 2));
    const int o_ = kt * 32;
    CPA16(d, xh + o_);
    CPA16(d + 16, xh + o_ + 8);
    CPA16(d + PLANE * 2, xl + o_);
    CPA16(d + PLANE * 2 + 16, xl + o_ + 8);
    CPA16(d + 2 * PLANE * 2, wh + o_);
    CPA16(d + 2 * PLANE * 2 + 16, wh + o_ + 8);
    CPA16(d + 3 * PLANE * 2, wl + o_);
    CPA16(d + 3 * PLANE * 2 + 16, wl + o_ + 8);
    CPA_COMMIT();
  }

  __device__ __forceinline__ void run(float acc[4][4][4]) {
    issue(0, 0);
    CPA_WAIT(0);
    __syncthreads();
    int buf = 0;
    for (int kt = 0; kt < 32; kt++) {
      if (kt < 31) issue(kt + 1, buf ^ 1);
      const unsigned bbase = sb32 + buf * (BUFE * 2);
#pragma unroll
      for (int ks = 0; ks < 2; ks++) {
        const int k0 = ks << 4;
        unsigned ahi[4][4], alo[4][4], bhi[2][4], blo[2][4];
        unsigned aaddr = bbase + (unsigned)((a_r * SA + k0 + a_c) << 1);
#pragma unroll
        for (int mf = 0; mf < 4; mf++) {
          LDSM4(ahi[mf], aaddr + mf * (16 * SA * 2));
          LDSM4(alo[mf], aaddr + mf * (16 * SA * 2) + PLANE * 2);
        }
        unsigned baddr =
            bbase + (unsigned)(((2 * PLANE) + b_r * SA + k0 + b_c) << 1);
#pragma unroll
        for (int nf2 = 0; nf2 < 2; nf2++) {
          LDSM4(bhi[nf2], baddr + nf2 * (16 * SA * 2));
          LDSM4(blo[nf2], baddr + nf2 * (16 * SA * 2) + PLANE * 2);
        }
#pragma unroll
        for (int c = 0; c < 3; c++)
#pragma unroll
          for (int mf = 0; mf < 4; mf++)
#pragma unroll
            for (int nf = 0; nf < 4; nf++) {
              const int g = nf >> 1, hh = (nf & 1) << 1;
              if (c == 0)
                MMA16816(acc[mf][nf], ahi[mf], bhi[g][hh], bhi[g][hh + 1]);
              else if (c == 1)
                MMA16816(acc[mf][nf], ahi[mf], blo[g][hh], blo[g][hh + 1]);
              else
                MMA16816(acc[mf][nf], alo[mf], bhi[g][hh], bhi[g][hh + 1]);
            }
      }
      if (kt < 31) {
        CPA_WAIT(0);
        __syncthreads();
        buf ^= 1;
      }
    }
  }
};

// ---------------------------------------------------------------------------
// Merged q/k/v projection GEMM. grid (8, 32, 3); z: 0=q(rope),1=k(rope),2=v.
// ---------------------------------------------------------------------------
__global__ __launch_bounds__(256, 2) void gemm_qkv(
    const __nv_bfloat16* __restrict__ Qh, const __nv_bfloat16* __restrict__ Ql,
    const __nv_bfloat16* __restrict__ Kh, const __nv_bfloat16* __restrict__ Kl,
    const __nv_bfloat16* __restrict__ Vh, const __nv_bfloat16* __restrict__ Vl,
    const __nv_bfloat16* __restrict__ Wqh, const __nv_bfloat16* __restrict__ Wql,
    const __nv_bfloat16* __restrict__ Wkh, const __nv_bfloat16* __restrict__ Wkl,
    const __nv_bfloat16* __restrict__ Wvh, const __nv_bfloat16* __restrict__ Wvl,
    __nv_bfloat16* __restrict__ Oqh, __nv_bfloat16* __restrict__ Oql,
    __nv_bfloat16* __restrict__ Okh, __nv_bfloat16* __restrict__ Okl,
    __nv_bfloat16* __restrict__ Ovh, __nv_bfloat16* __restrict__ Ovl,
    const float* __restrict__ CT, const float* __restrict__ ST) {
  extern __shared__ __nv_bfloat16 sb[];
  const int z = blockIdx.z;
  const __nv_bfloat16 *Xh, *Xl, *Wh, *Wl;
  __nv_bfloat16 *Yh, *Yl;
  if (z == 0) { Xh = Qh; Xl = Ql; Wh = Wqh; Wl = Wql; Yh = Oqh; Yl = Oql; }
  else if (z == 1) { Xh = Kh; Xl = Kl; Wh = Wkh; Wl = Wkl; Yh = Okh; Yl = Okl; }
  else { Xh = Vh; Xl = Vl; Wh = Wvh; Wl = Wvl; Yh = Ovh; Yl = Ovl; }

  const int t = threadIdx.x;
  const int lane = t & 31;
  const int w = t >> 5;
  const int m0 = blockIdx.y * 128;
  const int n0 = blockIdx.x * 128;

  GemmCore core;
  core.init(Xh, Xl, Wh, Wl, m0, n0,
            (unsigned)__cvta_generic_to_shared(sb), t);
  float acc[4][4][4] = {};
  core.run(acc);

  const int erow = m0 + (w & 1) * 64 + (lane >> 2);
  const int ecol = n0 + (w >> 1) * 32 + ((lane & 3) << 1);
  const bool dorope = (z < 2);
#pragma unroll
  for (int mf = 0; mf < 4; mf++)
#pragma unroll
    for (int nf = 0; nf < 4; nf++) {
      const int colbase = ecol + nf * 8;
      const int j = colbase & 63;
#pragma unroll
      for (int p = 0; p < 2; p++) {
        const int row = erow + mf * 16 + p * 8;
        float a0 = acc[mf][nf][2 * p], a1 = acc[mf][nf][2 * p + 1];
        if (dorope) {
          const int s = row & (SS - 1);
          float c0 = CT[s * 64 + j], s0v = ST[s * 64 + j];
          float c1 = CT[s * 64 + j + 1], s1v = ST[s * 64 + j + 1];
          float r0 = a0 * c0 - a1 * s0v;
          float r1 = a0 * s1v + a1 * c1;
          a0 = r0;
          a1 = r1;
        }
        __nv_bfloat16 ha = __float2bfloat16(a0), hb = __float2bfloat16(a1);
        size_t addr = (size_t)row * 1024 + colbase;
        *(unsigned*)&Yh[addr] = pack_bf16(a0, a1);
        *(unsigned*)&Yl[addr] = pack_bf16(a0 - __bfloat162float(ha),
                                          a1 - __bfloat162float(hb));
      }
    }
}

// ---------------------------------------------------------------------------
// Final projection GEMM: planes -> fp32 out.
// ---------------------------------------------------------------------------
__global__ __launch_bounds__(256, 2) void gemm_out(
    const __nv_bfloat16* __restrict__ Xh, const __nv_bfloat16* __restrict__ Xl,
    const __nv_bfloat16* __restrict__ Wh, const __nv_bfloat16* __restrict__ Wl,
    float* __restrict__ Y) {
  extern __shared__ __nv_bfloat16 sb[];
  const int t = threadIdx.x;
  const int lane = t & 31;
  const int w = t >> 5;
  const int m0 = blockIdx.y * 128;
  const int n0 = blockIdx.x * 128;

  GemmCore core;
  core.init(Xh, Xl, Wh, Wl, m0, n0,
            (unsigned)__cvta_generic_to_shared(sb), t);
  float acc[4][4][4] = {};
  core.run(acc);

  const int erow = m0 + (w & 1) * 64 + (lane >> 2);
  const int ecol = n0 + (w >> 1) * 32 + ((lane & 3) << 1);
#pragma unroll
  for (int mf = 0; mf < 4; mf++)
#pragma unroll
    for (int nf = 0; nf < 4; nf++) {
      float* yp = Y + (size_t)(erow + mf * 16) * 1024 + ecol + nf * 8;
      float2 lo2 = {acc[mf][nf][0], acc[mf][nf][1]};
      float2 hi2 = {acc[mf][nf][2], acc[mf][nf][3]};
      *(float2*)yp = lo2;
      *(float2*)(yp + 8 * 1024) = hi2;
    }
}

// ---------------------------------------------------------------------------
// MMA flash attention: causal, bf16x3, cp.async double buffered K/V.
// ---------------------------------------------------------------------------
#define AST 72
#define PL2 (64 * AST * 2)
#define STAGE_B (4 * PL2)
#define ATTN_SMEM (2 * STAGE_B)  // 73728 B

__global__ __launch_bounds__(128, 2) void attn_mma(
    const __nv_bfloat16* __restrict__ Qh, const __nv_bfloat16* __restrict__ Ql,
    const __nv_bfloat16* __restrict__ Kh, const __nv_bfloat16* __restrict__ Kl,
    const __nv_bfloat16* __restrict__ Vh, const __nv_bfloat16* __restrict__ Vl,
    __nv_bfloat16* __restrict__ XoH, __nv_bfloat16* __restrict__ XoL) {
  extern __shared__ __nv_bfloat16 as_[];
  const unsigned s_base = (unsigned)__cvta_generic_to_shared(as_);

  const int t = threadIdx.x;
  const int lane = t & 31;
  const int wi = t >> 5;
  const int b = blockIdx.x >> 4;
  const int h = blockIdx.x & 15;
  const int qt = (int)gridDim.y - 1 - (int)blockIdx.y;
  const size_t base = (size_t)b * SS * DD + h * DK;

  {
    __nv_bfloat16* q0h = as_;
    __nv_bfloat16* q0l = as_ + 64 * AST;
    for (int idx = t; idx < 512; idx += 128) {
      int r = idx >> 3, c = (idx & 7) << 3;
      size_t g = base + (size_t)(qt * 64 + r) * DD + c;
      *(uint4*)&q0h[r * AST + c] = *(const uint4*)&Qh[g];
      *(uint4*)&q0l[r * AST + c] = *(const uint4*)&Ql[g];
    }
  }
  __syncthreads();
  const int a_r = wi * 16 + (lane & 15);
  const int a_c = (lane & 16) ? 8 : 0;
  unsigned qfh[4][4], qfl[4][4];
#pragma unroll
  for (int kc = 0; kc < 4; kc++) {
    unsigned ad = s_base + (unsigned)((a_r * AST + kc * 16 + a_c) << 1);
    LDSM4(qfh[kc], ad);
    LDSM4(qfl[kc], ad + PL2);
  }
  __syncthreads();

  auto issue_tile = [&](int j, int bufi) {
    const unsigned kb = s_base + bufi * STAGE_B;
    for (int idx = t; idx < 512; idx += 128) {
      int r = idx >> 3, c = (idx & 7) << 3;
      size_t g = base + (size_t)(j * 64 + r) * DD + c;
      unsigned off = (unsigned)((r * AST + c) << 1);
      CPA16(kb + off, Kh + g);
      CPA16(kb + PL2 + off, Kl + g);
      CPA16(kb + 2 * PL2 + off, Vh + g);
      CPA16(kb + 3 * PL2 + off, Vl + g);
    }
    CPA_COMMIT();
  };

  const int b_r = (lane & 7) + ((lane & 16) ? 8 : 0);
  const int b_c = (lane & 8) ? 8 : 0;
  const int v_r = lane & 15;
  const int v_c = ((lane >> 4) & 1) << 3;

  float o[8][4] = {};
  float mrow[2] = {-INFINITY, -INFINITY};
  float lrow[2] = {0.f, 0.f};
  const int grow0 = qt * 64 + wi * 16 + (lane >> 2);
  const int gcol0 = (lane & 3) << 1;

  issue_tile(0, 0);
  int buf = 0;
  for (int j = 0; j <= qt; j++) {
    if (j < qt) {
      issue_tile(j + 1, buf ^ 1);
      CPA_WAIT(1);
    } else {
      CPA_WAIT(0);
    }
    __syncthreads();
    const unsigned kb = s_base + buf * STAGE_B;
    const unsigned vb = kb + 2 * PL2;

    float sc[8][4] = {};
#pragma unroll
    for (int kc = 0; kc < 4; kc++) {
      unsigned bh[4][4], bl[4][4];
#pragma unroll
      for (int g2 = 0; g2 < 4; g2++) {
        unsigned ad =
            kb + (unsigned)(((g2 * 16 + b_r) * AST + kc * 16 + b_c) << 1);
        LDSM4(bh[g2], ad);
        LDSM4(bl[g2], ad + PL2);
      }
#pragma unroll
      for (int c = 0; c < 3; c++)
#pragma unroll
        for (int nf = 0; nf < 8; nf++) {
          const int g2 = nf >> 1, hh = (nf & 1) << 1;
          if (c == 0)
            MMA16816(sc[nf], qfh[kc], bh[g2][hh], bh[g2][hh + 1]);
          else if (c == 1)
            MMA16816(sc[nf], qfh[kc], bl[g2][hh], bl[g2][hh + 1]);
          else
            MMA16816(sc[nf], qfl[kc], bh[g2][hh], bh[g2][hh + 1]);
        }
    }

    const float SC = 0.125f;
    if (j == qt) {
#pragma unroll
      for (int nf = 0; nf < 8; nf++)
#pragma unroll
        for (int e = 0; e < 4; e++) {
          int col = j * 64 + nf * 8 + gcol0 + (e & 1);
          int row = grow0 + ((e >> 1) << 3);
          sc[nf][e] = (col > row) ? -INFINITY : sc[nf][e] * SC;
        }
    } else {
#pragma unroll
      for (int nf = 0; nf < 8; nf++)
#pragma unroll
        for (int e = 0; e < 4; e++) sc[nf][e] *= SC;
    }

#pragma unroll
    for (int i = 0; i < 2; i++) {
      float tm = -INFINITY;
#pragma unroll
      for (int nf = 0; nf < 8; nf++)
        tm = fmaxf(tm, fmaxf(sc[nf][2 * i], sc[nf][2 * i + 1]));
      tm = fmaxf(tm, __shfl_xor_sync(0xffffffffu, tm, 1));
      tm = fmaxf(tm, __shfl_xor_sync(0xffffffffu, tm, 2));
      float mn = fmaxf(mrow[i], tm);
      float corr = __expf(mrow[i] - mn);
      float ps = 0.f;
#pragma unroll
      for (int nf = 0; nf < 8; nf++) {
        float p0 = __expf(sc[nf][2 * i] - mn);
        float p1 = __expf(sc[nf][2 * i + 1] - mn);
        sc[nf][2 * i] = p0;
        sc[nf][2 * i + 1] = p1;
        ps += p0 + p1;
      }
      ps += __shfl_xor_sync(0xffffffffu, ps, 1);
      ps += __shfl_xor_sync(0xffffffffu, ps, 2);
      lrow[i] = lrow[i] * corr + ps;
      mrow[i] = mn;
#pragma unroll
      for (int nf = 0; nf < 8; nf++) {
        o[nf][2 * i] *= corr;
        o[nf][2 * i + 1] *= corr;
      }
    }

#pragma unroll
    for (int kc = 0; kc < 4; kc++) {
      unsigned pa[4], pl[4];
#pragma unroll
      for (int rr = 0; rr < 2; rr++) {
        float f0 = sc[2 * kc + rr][0], f1 = sc[2 * kc + rr][1];
        float f2 = sc[2 * kc + rr][2], f3 = sc[2 * kc + rr][3];
        __nv_bfloat16 h0 = __float2bfloat16(f0), h1 = __float2bfloat16(f1);
        __nv_bfloat16 h2 = __float2bfloat16(f2), h3 = __float2bfloat16(f3);
        pa[2 * rr] = pack_bf16(f0, f1);
        pa[2 * rr + 1] = pack_bf16(f2, f3);
        pl[2 * rr] = pack_bf16(f0 - __bfloat162float(h0),
                               f1 - __bfloat162float(h1));
        pl[2 * rr + 1] = pack_bf16(f2 - __bfloat162float(h2),
                                   f3 - __bfloat162float(h3));
      }
      unsigned wvh[4][4], wvl[4][4];
#pragma unroll
      for (int g2 = 0; g2 < 4; g2++) {
        unsigned ad =
            vb + (unsigned)(((kc * 16 + v_r) * AST + g2 * 16 + v_c) << 1);
        LDSM4T(wvh[g2], ad);
        LDSM4T(wvl[g2], ad + PL2);
      }
#pragma unroll
      for (int c = 0; c < 3; c++)
#pragma unroll
        for (int nf = 0; nf < 8; nf++) {
          const int g2 = nf >> 1, hh = (nf & 1) << 1;
          if (c == 0)
            MMA16816(o[nf], pa, wvh[g2][hh], wvh[g2][hh + 1]);
          else if (c == 1)
            MMA16816(o[nf], pa, wvl[g2][hh], wvl[g2][hh + 1]);
          else
            MMA16816(o[nf], pl, wvh[g2][hh], wvh[g2][hh + 1]);
        }
    }
    __syncthreads();
    buf ^= 1;
  }

#pragma unroll
  for (int i = 0; i < 2; i++) {
    float inv = 1.f / lrow[i];
    int row = grow0 + i * 8;
#pragma unroll
    for (int nf = 0; nf < 8; nf++) {
      float a = o[nf][2 * i] * inv, b2 = o[nf][2 * i + 1] * inv;
      __nv_bfloat16 ha = __float2bfloat16(a), hb = __float2bfloat16(b2);
      size_t addr = (size_t)(b * SS + row) * DD + h * DK + nf * 8 + gcol0;
      *(unsigned*)&XoH[addr] = pack_bf16(a, b2);
      *(unsigned*)&XoL[addr] =
          pack_bf16(a - __bfloat162float(ha), b2 - __bfloat162float(hb));
    }
  }
}

// ---------------------------------------------------------------------------
// kernel_launch
// Inputs: 0=q, 1=k, 2=v, 3=mask (ignored: tril causal), 4=wq, 5=wk, 6=wv, 7=wo
// ---------------------------------------------------------------------------
extern "C" void kernel_launch(void* const* d_in, const int* in_sizes, int n_in,
                              void* d_out, int out_size) {
  (void)in_sizes; (void)n_in; (void)out_size;
  const float* q = (const float*)d_in[0];
  const float* k = (const float*)d_in[1];
  const float* v = (const float*)d_in[2];
  const float* wq = (const float*)d_in[4];
  const float* wk = (const float*)d_in[5];
  const float* wv = (const float*)d_in[6];
  const float* wo = (const float*)d_in[7];
  float* out = (float*)d_out;

  __nv_bfloat16 *qh, *ql, *kh, *kl, *vh, *vl;
  __nv_bfloat16 *oqh, *oql, *okh, *okl, *xh, *xl, *yh, *yl;
  cudaGetSymbolAddress((void**)&qh, g_qh); cudaGetSymbolAddress((void**)&ql, g_ql);
  cudaGetSymbolAddress((void**)&kh, g_kh); cudaGetSymbolAddress((void**)&kl, g_kl);
  cudaGetSymbolAddress((void**)&vh, g_vh); cudaGetSymbolAddress((void**)&vl, g_vl);
  cudaGetSymbolAddress((void**)&oqh, g_oqh); cudaGetSymbolAddress((void**)&oql, g_oql);
  cudaGetSymbolAddress((void**)&okh, g_okh); cudaGetSymbolAddress((void**)&okl, g_okl);
  cudaGetSymbolAddress((void**)&xh, g_xh); cudaGetSymbolAddress((void**)&xl, g_xl);
  cudaGetSymbolAddress((void**)&yh, g_yh); cudaGetSymbolAddress((void**)&yl, g_yl);
  __nv_bfloat16 *wqh, *wql, *wkh, *wkl, *wvh, *wvl, *woh, *wol;
  cudaGetSymbolAddress((void**)&wqh, g_wqh); cudaGetSymbolAddress((void**)&wql, g_wql);
  cudaGetSymbolAddress((void**)&wkh, g_wkh); cudaGetSymbolAddress((void**)&wkl, g_wkl);
  cudaGetSymbolAddress((void**)&wvh, g_wvh); cudaGetSymbolAddress((void**)&wvl, g_wvl);
  cudaGetSymbolAddress((void**)&woh, g_woh); cudaGetSymbolAddress((void**)&wol, g_wol);
  float *ct, *st;
  cudaGetSymbolAddress((void**)&ct, g_ct);
  cudaGetSymbolAddress((void**)&st, g_st);

  cudaFuncSetAttribute(gemm_qkv, cudaFuncAttributeMaxDynamicSharedMemorySize,
                       GEMM_SMEM);
  cudaFuncSetAttribute(gemm_out, cudaFuncAttributeMaxDynamicSharedMemorySize,
                       GEMM_SMEM);
  cudaFuncSetAttribute(attn_mma, cudaFuncAttributeMaxDynamicSharedMemorySize,
                       ATTN_SMEM);

  // one prep launch: all splits + rope tables
  prep_kernel<<<dim3(NEL / 1024, 1, 8), 256>>>(
      q, k, v, wq, wk, wv, wo, qh, ql, kh, kl, vh, vl, wqh, wql, wkh, wkl, wvh,
      wvl, woh, wol, ct, st);

  // fused q/k/v projections (+rope on q/k), bf16 plane outputs
  gemm_qkv<<<dim3(8, 32, 3), 256, GEMM_SMEM>>>(
      qh, ql, kh, kl, vh, vl, wqh, wql, wkh, wkl, wvh, wvl, oqh, oql, okh, okl,
      xh, xl, ct, st);

  // attention
  attn_mma<<<dim3(BB * HH, SS / 64), 128, ATTN_SMEM>>>(oqh, oql, okh, okl, xh,
                                                       xl, yh, yl);

  // output projection
  gemm_out<<<dim3(8, 32), 256, GEMM_SMEM>>>(yh, yl, woh, wol, out);
}